// round 10
// baseline (speedup 1.0000x reference)
#include <cuda_runtime.h>
#include <cstdint>
#include <float.h>

// Problem constants
#define B_ 64
#define T_ 2048
#define F_ 256
#define U_ 32

// ---------------------------------------------------------------------------
// Scratch (static device globals; no allocation allowed)
// ---------------------------------------------------------------------------
__device__ float         g_pot [B_ * T_ * U_];   // 16 MB
__device__ unsigned char g_bp  [B_ * T_ * U_];   //  4 MB
__device__ int           g_last[B_];

// ---------------------------------------------------------------------------
// K1: potentials — one warp per (b,t) row, maximally simple.
//   pot[row][u] = sum_f x[row][f] * kernel[f][u] + bias[u] (+boundaries)
// ---------------------------------------------------------------------------
__global__ void k1_pot(const float* __restrict__ x, const float* __restrict__ kern,
                       const float* __restrict__ bias, const float* __restrict__ lb,
                       const float* __restrict__ rb) {
    const int warpsPerBlock = blockDim.x >> 5;
    const int row  = blockIdx.x * warpsPerBlock + (threadIdx.x >> 5);
    const int u    = threadIdx.x & 31;
    if (row >= B_ * T_) return;

    const float* xr = x + (size_t)row * F_;
    float acc = 0.0f;
    #pragma unroll 8
    for (int f = 0; f < F_; f++) {
        acc = fmaf(__ldg(&xr[f]), __ldg(&kern[f * U_ + u]), acc);
    }

    const int t = row & (T_ - 1);   // T_ is a power of two; row = b*T_ + t
    float val = acc + bias[u];
    if (t == 0)      val += lb[u];
    if (t == T_ - 1) val += rb[u];
    g_pot[(size_t)row * U_ + u] = val;
}

// ---------------------------------------------------------------------------
// K2: Viterbi forward — one warp per batch, explicit per-lane argmax.
//   Lane u: new_state[u] = max_v(state[v] + chain[v][u]) + pot[t][u]
//   state[v] via __shfl_sync; ascending v with strict '>' keeps the FIRST
//   maximal index (jnp.argmax semantics).
// ---------------------------------------------------------------------------
__global__ void k2_forward(const float* __restrict__ chain) {
    const int b = blockIdx.x;
    const int u = threadIdx.x;
    const unsigned FULL = 0xffffffffu;

    float cT[U_];                        // cT[v] = chain[v][u]
    #pragma unroll
    for (int v = 0; v < U_; v++) cT[v] = chain[v * U_ + u];

    const float*   pb  = g_pot + (size_t)b * T_ * U_;
    unsigned char* bpb = g_bp  + (size_t)b * T_ * U_;

    float s = pb[u];                     // state at t=0

    for (int t = 1; t < T_; t++) {
        float best = -FLT_MAX;
        int   bi   = 0;
        #pragma unroll
        for (int v = 0; v < U_; v++) {
            float sv = __shfl_sync(FULL, s, v);
            float c  = sv + cT[v];
            if (c > best) { best = c; bi = v; }
        }
        bpb[(size_t)t * U_ + u] = (unsigned char)bi;
        s = best + pb[(size_t)t * U_ + u];
    }

    // last_tag = argmax over lanes (first index on ties), computed uniformly.
    float m  = -FLT_MAX;
    int   mi = 0;
    #pragma unroll
    for (int v = 0; v < U_; v++) {
        float sv = __shfl_sync(FULL, s, v);
        if (sv > m) { m = sv; mi = v; }
    }
    if (u == 0) g_last[b] = mi;
}

// ---------------------------------------------------------------------------
// K3: serial backtrack — one thread per batch (64 independent chains).
//   tag[T-1] = last; tag[t-1] = bp[t][tag[t]].
//   *** OUTPUT WRITTEN AS FLOAT32 *** (Round-9 experiment: int32 writes have
//   produced exact rel_err=1.0 across six algorithmically distinct kernels —
//   the signature of tags being reinterpreted as float denormals ≈ 0).
// ---------------------------------------------------------------------------
__global__ void k3_back(float* __restrict__ out) {
    const int b = blockIdx.x * blockDim.x + threadIdx.x;
    if (b >= B_) return;

    const unsigned char* bpb = g_bp + (size_t)b * T_ * U_;
    int tag = g_last[b] & 31;
    out[b * T_ + (T_ - 1)] = (float)tag;
    for (int t = T_ - 1; t >= 1; t--) {
        tag = bpb[(size_t)t * U_ + tag] & 31;
        out[b * T_ + (t - 1)] = (float)tag;
    }
}

// ---------------------------------------------------------------------------
// Launch — RANK-BASED input identification (unit-free: correct whether
// in_sizes is element counts or byte counts, and for any metadata ordering).
// Stable sort keeps the three equal-size U-vectors in original relative
// order: (bias, left_boundary, right_boundary) under dict-insertion,
// signature, and alphabetical orderings alike.
// ---------------------------------------------------------------------------
extern "C" void kernel_launch(void* const* d_in, const int* in_sizes, int n_in,
                              void* d_out, int out_size) {
    int idx[16];
    int n = (n_in < 16) ? n_in : 16;
    for (int i = 0; i < n; i++) idx[i] = i;
    for (int i = 1; i < n; i++) {                 // stable insertion sort, desc
        int cur = idx[i];
        int j = i - 1;
        while (j >= 0 && in_sizes[idx[j]] < in_sizes[cur]) {
            idx[j + 1] = idx[j];
            j--;
        }
        idx[j + 1] = cur;
    }

    const float* x     = (const float*)d_in[idx[0]];
    const float* kern  = (const float*)d_in[idx[1]];
    const float* chain = (const float*)d_in[idx[2]];
    const float* bias  = (const float*)d_in[idx[3]];
    const float* lb    = (const float*)d_in[idx[4]];
    const float* rb    = (const float*)d_in[idx[5]];
    float* out = (float*)d_out;

    // K1: one warp per row; 8 warps per block.
    k1_pot    <<<(B_ * T_) / 8, 256>>>(x, kern, bias, lb, rb);
    k2_forward<<<B_, 32>>>(chain);
    k3_back   <<<2, 32>>>(out);
}

// round 11
// speedup vs baseline: 1.8291x; 1.8291x over previous
#include <cuda_runtime.h>
#include <cstdint>
#include <float.h>

// Problem constants
#define B_ 64
#define T_ 2048
#define F_ 256
#define U_ 32

// ---------------------------------------------------------------------------
// Scratch (static device globals; no allocation allowed)
// ---------------------------------------------------------------------------
__device__ float         g_pot   [B_ * T_ * U_];   // 16 MB
__device__ float         g_states[B_ * T_ * U_];   // 16 MB
__device__ unsigned char g_bp    [B_ * T_ * U_];   //  4 MB
__device__ int           g_last  [B_];

// ---------------------------------------------------------------------------
// K1: potentials  pot[b,t,u] = dot(x[b,t,:], kernel[:,u]) + bias[u] (+bounds)
//   128 threads (4 warps). Kernel matrix in smem (32KB), each warp stages
//   2 x-rows (f-major) and each lane accumulates u=lane for both rows.
// ---------------------------------------------------------------------------
__global__ void k1_pot(const float* __restrict__ x, const float* __restrict__ kern,
                       const float* __restrict__ bias, const float* __restrict__ lb,
                       const float* __restrict__ rb) {
    __shared__ __align__(16) float kk[F_ * U_];   // kk[f*32+u] = kernel[f][u]
    __shared__ __align__(16) float xs[4][F_][2];  // per-warp, 2 rows, f-major

    const int tid  = threadIdx.x;
    const int w    = tid >> 5;
    const int lane = tid & 31;

    for (int i = tid; i < F_ * U_; i += 128) kk[i] = kern[i];
    const float bv  = bias[lane];
    const float lbv = lb[lane];
    const float rbv = rb[lane];
    __syncthreads();

    const int pairGlobal = blockIdx.x * 4 + w;
    const int nPairs     = gridDim.x * 4;

    for (int q = pairGlobal; q < (B_ * T_) / 2; q += nPairs) {
        const int row0 = q * 2;

        #pragma unroll
        for (int i = 0; i < 2; i++) {
            const float4* xr = (const float4*)(x + (size_t)(row0 + i) * F_);
            float4 a = xr[lane];
            float4 b = xr[lane + 32];
            xs[w][4 * lane + 0][i] = a.x;
            xs[w][4 * lane + 1][i] = a.y;
            xs[w][4 * lane + 2][i] = a.z;
            xs[w][4 * lane + 3][i] = a.w;
            xs[w][128 + 4 * lane + 0][i] = b.x;
            xs[w][128 + 4 * lane + 1][i] = b.y;
            xs[w][128 + 4 * lane + 2][i] = b.z;
            xs[w][128 + 4 * lane + 3][i] = b.w;
        }
        __syncwarp();

        float acc0 = 0.0f, acc1 = 0.0f;
        #pragma unroll 8
        for (int f = 0; f < F_; f++) {
            float kv = kk[f * U_ + lane];
            acc0 = fmaf(xs[w][f][0], kv, acc0);
            acc1 = fmaf(xs[w][f][1], kv, acc1);
        }

        #pragma unroll
        for (int i = 0; i < 2; i++) {
            int   row = row0 + i;
            int   t   = row & (T_ - 1);
            float val = (i == 0 ? acc0 : acc1) + bv;
            if (t == 0)      val += lbv;
            if (t == T_ - 1) val += rbv;
            g_pot[(size_t)row * U_ + lane] = val;
        }
        __syncwarp();
    }
}

// ---------------------------------------------------------------------------
// K2: Viterbi forward (max only, no argmax). One warp per batch.
//   state[t][u] streamed to g_states for parallel bp recompute later.
// ---------------------------------------------------------------------------
__global__ void k2_forward(const float* __restrict__ chain) {
    const int b = blockIdx.x;
    const int u = threadIdx.x;

    __shared__ __align__(16) float st[2][U_];

    float cT[U_];
    #pragma unroll
    for (int v = 0; v < U_; v++) cT[v] = chain[v * U_ + u];

    const float* pb = g_pot    + (size_t)b * T_ * U_;
    float*       sb = g_states + (size_t)b * T_ * U_;

    float s = pb[u];
    sb[u] = s;
    st[0][u] = s;
    __syncwarp();

    const int PF = 8;
    float pf[PF];
    #pragma unroll
    for (int i = 0; i < PF; i++) pf[i] = pb[(size_t)(1 + i) * U_ + u];

    for (int t = 1; t < T_; t++) {
        const int wr = t & 1, rd = wr ^ 1;
        float c[U_];
        #pragma unroll
        for (int qd = 0; qd < 8; qd++) {
            float4 a4 = *(const float4*)&st[rd][qd * 4];
            c[qd * 4 + 0] = a4.x + cT[qd * 4 + 0];
            c[qd * 4 + 1] = a4.y + cT[qd * 4 + 1];
            c[qd * 4 + 2] = a4.z + cT[qd * 4 + 2];
            c[qd * 4 + 3] = a4.w + cT[qd * 4 + 3];
        }
        #pragma unroll
        for (int s2 = 16; s2 >= 1; s2 >>= 1)
            #pragma unroll
            for (int i = 0; i < 16; i++)
                if (i < s2) c[i] = fmaxf(c[i], c[i + s2]);

        float pv = pf[(t - 1) & 7];
        if (t + PF < T_) pf[(t - 1) & 7] = pb[(size_t)(t + PF) * U_ + u];

        float ns = c[0] + pv;
        st[wr][u] = ns;
        sb[(size_t)t * U_ + u] = ns;
        s = ns;
        __syncwarp();
    }

    // last_tag = argmax over lanes (first index on ties)
    float m = s;
    #pragma unroll
    for (int o = 16; o; o >>= 1) m = fmaxf(m, __shfl_xor_sync(0xffffffffu, m, o));
    unsigned mask = __ballot_sync(0xffffffffu, s == m);
    if (u == 0) {
        int ff = __ffs(mask);
        g_last[b] = (ff > 0) ? (ff - 1) : 0;
    }
}

// ---------------------------------------------------------------------------
// K3: backpointer recompute (parallel over all (b,t), t>=1)
//   bp[b,t,u] = argmax_v(state[b,t-1,v] + chain[v,u])  (pot-independent;
//   strict '>' ascending v = first-index ties, matching jnp.argmax).
// ---------------------------------------------------------------------------
__global__ void k3_bp(const float* __restrict__ chain) {
    const int lane = threadIdx.x & 31;
    const int wInB = threadIdx.x >> 5;
    const int warp = (blockIdx.x * blockDim.x + threadIdx.x) >> 5;
    const int nwarp = (gridDim.x * blockDim.x) >> 5;

    __shared__ __align__(16) float srow[8][U_];

    float cT[U_];
    #pragma unroll
    for (int v = 0; v < U_; v++) cT[v] = chain[v * U_ + lane];

    const int total = B_ * (T_ - 1);
    for (int i = warp; i < total; i += nwarp) {
        const int b = i / (T_ - 1);
        const int t = i % (T_ - 1) + 1;
        float sv = g_states[((size_t)b * T_ + (t - 1)) * U_ + lane];
        srow[wInB][lane] = sv;
        __syncwarp();

        float best = srow[wInB][0] + cT[0];
        int   bi = 0;
        #pragma unroll
        for (int v = 1; v < U_; v++) {
            float cc = srow[wInB][v] + cT[v];
            if (cc > best) { best = cc; bi = v; }
        }
        g_bp[((size_t)b * T_ + t) * U_ + lane] = (unsigned char)bi;
        __syncwarp();
    }
}

// ---------------------------------------------------------------------------
// K4: parallel backtrack via suffix composition of bp functions.
//   One block per batch, 32 warps of 64-step chunks. Pass 1 builds chunk
//   compositions C[w]; one thread chains chunk-entry tags ev[w]; pass 2
//   re-composes and emits tags. OUTPUT IS FLOAT32.
// ---------------------------------------------------------------------------
__global__ void k4_back(float* __restrict__ out) {
    __shared__ unsigned char C[32][32];
    __shared__ int ev[32];

    const int b    = blockIdx.x;
    const int tid  = threadIdx.x;
    const int w    = tid >> 5;
    const int lane = tid & 31;

    const int tstart = w * 64 + 1;
    const int tend   = min(w * 64 + 64, T_ - 1);

    const unsigned char* bpb = g_bp + (size_t)b * T_ * U_;

    // Pass 1: f <- bp[t] o f  for t = tend..tstart (descending).
    int f = lane;
    for (int t = tend; t >= tstart; t--) {
        int g = bpb[(size_t)t * U_ + lane] & 31;
        f = __shfl_sync(0xffffffffu, g, f);
    }
    C[w][lane] = (unsigned char)f;
    __syncthreads();

    // ev[w] = tag entering chunk w from the right (tag at t = tend_w).
    if (tid == 0) {
        int v = g_last[b] & 31;
        ev[31] = v;
        for (int w2 = 30; w2 >= 0; w2--) {
            v = C[w2 + 1][v] & 31;
            ev[w2] = v;
        }
        out[b * T_ + (T_ - 1)] = (float)(g_last[b] & 31);
    }
    __syncthreads();

    // Pass 2: re-compose, emitting out[t-1] = (bp[t] o ... o bp[tend])(ev[w]).
    const int e = ev[w];
    f = lane;
    for (int t = tend; t >= tstart; t--) {
        int g = bpb[(size_t)t * U_ + lane] & 31;
        f = __shfl_sync(0xffffffffu, g, f);
        int tag = __shfl_sync(0xffffffffu, f, e);
        if (lane == 0) out[b * T_ + (t - 1)] = (float)tag;
    }
}

// ---------------------------------------------------------------------------
// Launch — RANK-BASED input identification (unit-free). Stable sort keeps
// the three equal-size U-vectors in original relative order:
// (bias, left_boundary, right_boundary).
// ---------------------------------------------------------------------------
extern "C" void kernel_launch(void* const* d_in, const int* in_sizes, int n_in,
                              void* d_out, int out_size) {
    int idx[16];
    int n = (n_in < 16) ? n_in : 16;
    for (int i = 0; i < n; i++) idx[i] = i;
    for (int i = 1; i < n; i++) {                 // stable insertion sort, desc
        int cur = idx[i];
        int j = i - 1;
        while (j >= 0 && in_sizes[idx[j]] < in_sizes[cur]) {
            idx[j + 1] = idx[j];
            j--;
        }
        idx[j + 1] = cur;
    }

    const float* x     = (const float*)d_in[idx[0]];
    const float* kern  = (const float*)d_in[idx[1]];
    const float* chain = (const float*)d_in[idx[2]];
    const float* bias  = (const float*)d_in[idx[3]];
    const float* lb    = (const float*)d_in[idx[4]];
    const float* rb    = (const float*)d_in[idx[5]];
    float* out = (float*)d_out;

    k1_pot    <<<1024, 128>>>(x, kern, bias, lb, rb);
    k2_forward<<<B_, 32>>>(chain);
    k3_bp     <<<512, 256>>>(chain);
    k4_back   <<<B_, 1024>>>(out);
}

// round 12
// speedup vs baseline: 4.5127x; 2.4672x over previous
#include <cuda_runtime.h>
#include <cstdint>
#include <float.h>

// Problem constants
#define B_ 64
#define T_ 2048
#define F_ 256
#define U_ 32

// ---------------------------------------------------------------------------
// Scratch (static device globals; no allocation allowed)
// ---------------------------------------------------------------------------
__device__ float         g_pot   [B_ * T_ * U_];   // 16 MB
__device__ float         g_states[B_ * T_ * U_];   // 16 MB
__device__ unsigned char g_bp    [B_ * T_ * U_];   //  4 MB
__device__ int           g_last  [B_];

// ---------------------------------------------------------------------------
// K1: potentials  pot[b,t,u] = dot(x[b,t,:], kernel[:,u]) + bias[u] (+bounds)
//   128 threads (4 warps). Kernel matrix in smem (32KB), each warp stages
//   2 x-rows (f-major) and each lane accumulates u=lane for both rows.
// ---------------------------------------------------------------------------
__global__ void k1_pot(const float* __restrict__ x, const float* __restrict__ kern,
                       const float* __restrict__ bias, const float* __restrict__ lb,
                       const float* __restrict__ rb) {
    __shared__ __align__(16) float kk[F_ * U_];   // kk[f*32+u] = kernel[f][u]
    __shared__ __align__(16) float xs[4][F_][2];  // per-warp, 2 rows, f-major

    const int tid  = threadIdx.x;
    const int w    = tid >> 5;
    const int lane = tid & 31;

    for (int i = tid; i < F_ * U_; i += 128) kk[i] = kern[i];
    const float bv  = bias[lane];
    const float lbv = lb[lane];
    const float rbv = rb[lane];
    __syncthreads();

    const int pairGlobal = blockIdx.x * 4 + w;
    const int nPairs     = gridDim.x * 4;

    for (int q = pairGlobal; q < (B_ * T_) / 2; q += nPairs) {
        const int row0 = q * 2;

        #pragma unroll
        for (int i = 0; i < 2; i++) {
            const float4* xr = (const float4*)(x + (size_t)(row0 + i) * F_);
            float4 a = xr[lane];
            float4 b = xr[lane + 32];
            xs[w][4 * lane + 0][i] = a.x;
            xs[w][4 * lane + 1][i] = a.y;
            xs[w][4 * lane + 2][i] = a.z;
            xs[w][4 * lane + 3][i] = a.w;
            xs[w][128 + 4 * lane + 0][i] = b.x;
            xs[w][128 + 4 * lane + 1][i] = b.y;
            xs[w][128 + 4 * lane + 2][i] = b.z;
            xs[w][128 + 4 * lane + 3][i] = b.w;
        }
        __syncwarp();

        float acc0 = 0.0f, acc1 = 0.0f;
        #pragma unroll 8
        for (int f = 0; f < F_; f++) {
            float kv = kk[f * U_ + lane];
            acc0 = fmaf(xs[w][f][0], kv, acc0);
            acc1 = fmaf(xs[w][f][1], kv, acc1);
        }

        #pragma unroll
        for (int i = 0; i < 2; i++) {
            int   row = row0 + i;
            int   t   = row & (T_ - 1);
            float val = (i == 0 ? acc0 : acc1) + bv;
            if (t == 0)      val += lbv;
            if (t == T_ - 1) val += rbv;
            g_pot[(size_t)row * U_ + lane] = val;
        }
        __syncwarp();
    }
}

// ---------------------------------------------------------------------------
// K2: Viterbi forward (max only). One warp per batch.
//   CRITICAL: the t-loop is chunked by 8 with a fully unrolled inner loop so
//   the prefetch pipeline pf[0..7] has only compile-time indices (registers,
//   not local memory — the Round-11 version's dynamic ring index spilled).
// ---------------------------------------------------------------------------
__device__ __forceinline__ void k2_step(int t, float pv, float (&st)[2][U_],
                                        const float (&cT)[U_], float* __restrict__ sb,
                                        int u, float& s_out) {
    const int wr = t & 1, rd = wr ^ 1;
    float c[U_];
    #pragma unroll
    for (int qd = 0; qd < 8; qd++) {
        float4 a4 = *(const float4*)&st[rd][qd * 4];
        c[qd * 4 + 0] = a4.x + cT[qd * 4 + 0];
        c[qd * 4 + 1] = a4.y + cT[qd * 4 + 1];
        c[qd * 4 + 2] = a4.z + cT[qd * 4 + 2];
        c[qd * 4 + 3] = a4.w + cT[qd * 4 + 3];
    }
    #pragma unroll
    for (int s2 = 16; s2 >= 1; s2 >>= 1)
        #pragma unroll
        for (int i = 0; i < 16; i++)
            if (i < s2) c[i] = fmaxf(c[i], c[i + s2]);

    const float ns = c[0] + pv;
    st[wr][u] = ns;
    sb[(size_t)t * U_ + u] = ns;
    s_out = ns;
    __syncwarp();
}

__global__ void k2_forward(const float* __restrict__ chain) {
    const int b = blockIdx.x;
    const int u = threadIdx.x;

    __shared__ __align__(16) float st[2][U_];

    float cT[U_];
    #pragma unroll
    for (int v = 0; v < U_; v++) cT[v] = chain[v * U_ + u];

    const float* pb = g_pot    + (size_t)b * T_ * U_;
    float*       sb = g_states + (size_t)b * T_ * U_;

    float s = pb[u];
    sb[u] = s;
    st[0][u] = s;
    __syncwarp();

    // Depth-8 register prefetch pipeline (all indices compile-time).
    float pf[8];
    #pragma unroll
    for (int i = 0; i < 8; i++) pf[i] = pb[(size_t)(1 + i) * U_ + u];

    int t = 1;
    // Main: 255 chunks of 8 covering t = 1..2040.
    for (; t + 8 <= T_; t += 8) {
        #pragma unroll
        for (int k = 0; k < 8; k++) {
            k2_step(t + k, pf[k], st, cT, sb, u, s);
            if (t + k + 8 < T_) pf[k] = pb[(size_t)(t + k + 8) * U_ + u];
        }
    }
    // Tail: t = 2041..2047 (7 steps), fully unrolled, static pf indices.
    #pragma unroll
    for (int k = 0; k < 7; k++) {
        k2_step(t + k, pf[k], st, cT, sb, u, s);
    }

    // last_tag = argmax over lanes (first index on ties)
    float m = s;
    #pragma unroll
    for (int o = 16; o; o >>= 1) m = fmaxf(m, __shfl_xor_sync(0xffffffffu, m, o));
    unsigned mask = __ballot_sync(0xffffffffu, s == m);
    if (u == 0) {
        int ff = __ffs(mask);
        g_last[b] = (ff > 0) ? (ff - 1) : 0;
    }
}

// ---------------------------------------------------------------------------
// K3: backpointer recompute (parallel over all (b,t), t>=1)
//   bp[b,t,u] = argmax_v(state[b,t-1,v] + chain[v,u])  (pot-independent;
//   strict '>' ascending v = first-index ties, matching jnp.argmax).
// ---------------------------------------------------------------------------
__global__ void k3_bp(const float* __restrict__ chain) {
    const int lane = threadIdx.x & 31;
    const int wInB = threadIdx.x >> 5;
    const int warp = (blockIdx.x * blockDim.x + threadIdx.x) >> 5;
    const int nwarp = (gridDim.x * blockDim.x) >> 5;

    __shared__ __align__(16) float srow[8][U_];

    float cT[U_];
    #pragma unroll
    for (int v = 0; v < U_; v++) cT[v] = chain[v * U_ + lane];

    const int total = B_ * (T_ - 1);
    for (int i = warp; i < total; i += nwarp) {
        const int b = i / (T_ - 1);
        const int t = i % (T_ - 1) + 1;
        float sv = g_states[((size_t)b * T_ + (t - 1)) * U_ + lane];
        srow[wInB][lane] = sv;
        __syncwarp();

        float best = srow[wInB][0] + cT[0];
        int   bi = 0;
        #pragma unroll
        for (int v = 1; v < U_; v++) {
            float cc = srow[wInB][v] + cT[v];
            if (cc > best) { best = cc; bi = v; }
        }
        g_bp[((size_t)b * T_ + t) * U_ + lane] = (unsigned char)bi;
        __syncwarp();
    }
}

// ---------------------------------------------------------------------------
// K4: parallel backtrack via suffix composition of bp functions.
//   One block per batch, 32 warps of 64-step chunks. OUTPUT IS FLOAT32.
// ---------------------------------------------------------------------------
__global__ void k4_back(float* __restrict__ out) {
    __shared__ unsigned char C[32][32];
    __shared__ int ev[32];

    const int b    = blockIdx.x;
    const int tid  = threadIdx.x;
    const int w    = tid >> 5;
    const int lane = tid & 31;

    const int tstart = w * 64 + 1;
    const int tend   = min(w * 64 + 64, T_ - 1);

    const unsigned char* bpb = g_bp + (size_t)b * T_ * U_;

    // Pass 1: f <- bp[t] o f  for t = tend..tstart (descending).
    int f = lane;
    for (int t = tend; t >= tstart; t--) {
        int g = bpb[(size_t)t * U_ + lane] & 31;
        f = __shfl_sync(0xffffffffu, g, f);
    }
    C[w][lane] = (unsigned char)f;
    __syncthreads();

    // ev[w] = tag entering chunk w from the right (tag at t = tend_w).
    if (tid == 0) {
        int v = g_last[b] & 31;
        ev[31] = v;
        for (int w2 = 30; w2 >= 0; w2--) {
            v = C[w2 + 1][v] & 31;
            ev[w2] = v;
        }
        out[b * T_ + (T_ - 1)] = (float)(g_last[b] & 31);
    }
    __syncthreads();

    // Pass 2: re-compose, emitting out[t-1] = (bp[t] o ... o bp[tend])(ev[w]).
    const int e = ev[w];
    f = lane;
    for (int t = tend; t >= tstart; t--) {
        int g = bpb[(size_t)t * U_ + lane] & 31;
        f = __shfl_sync(0xffffffffu, g, f);
        int tag = __shfl_sync(0xffffffffu, f, e);
        if (lane == 0) out[b * T_ + (t - 1)] = (float)tag;
    }
}

// ---------------------------------------------------------------------------
// Launch — RANK-BASED input identification (unit-free). Stable sort keeps
// the three equal-size U-vectors in original relative order:
// (bias, left_boundary, right_boundary).
// ---------------------------------------------------------------------------
extern "C" void kernel_launch(void* const* d_in, const int* in_sizes, int n_in,
                              void* d_out, int out_size) {
    int idx[16];
    int n = (n_in < 16) ? n_in : 16;
    for (int i = 0; i < n; i++) idx[i] = i;
    for (int i = 1; i < n; i++) {                 // stable insertion sort, desc
        int cur = idx[i];
        int j = i - 1;
        while (j >= 0 && in_sizes[idx[j]] < in_sizes[cur]) {
            idx[j + 1] = idx[j];
            j--;
        }
        idx[j + 1] = cur;
    }

    const float* x     = (const float*)d_in[idx[0]];
    const float* kern  = (const float*)d_in[idx[1]];
    const float* chain = (const float*)d_in[idx[2]];
    const float* bias  = (const float*)d_in[idx[3]];
    const float* lb    = (const float*)d_in[idx[4]];
    const float* rb    = (const float*)d_in[idx[5]];
    float* out = (float*)d_out;

    k1_pot    <<<1024, 128>>>(x, kern, bias, lb, rb);
    k2_forward<<<B_, 32>>>(chain);
    k3_bp     <<<1024, 256>>>(chain);
    k4_back   <<<B_, 1024>>>(out);
}